// round 1
// baseline (speedup 1.0000x reference)
#include <cuda_runtime.h>
#include <math.h>

// Max scores table: H=16 heads, up to S=4096 -> 2S+1 = 8193 entries/head.
#define H_FIXED 16
#define K_FIXED 5
#define MAX_SCORE_ELEMS (H_FIXED * (2 * 4096 + 1))

__device__ float g_scores[MAX_SCORE_ELEMS];

// Kernel 1: scores[h, r] = sum_k amp[k,h] * exp(-|w[k,h]| * (off[k,h] - (r-S))^2)
__global__ void tisa_scores_kernel(const float* __restrict__ off,
                                   const float* __restrict__ wid,
                                   const float* __restrict__ amp,
                                   int S) {
    const int total = H_FIXED * (2 * S + 1);
    int idx = blockIdx.x * blockDim.x + threadIdx.x;
    if (idx >= total) return;
    const int L = 2 * S + 1;
    int h = idx / L;
    int r = idx - h * L;
    float rel = (float)(r - S);
    float sum = 0.0f;
#pragma unroll
    for (int k = 0; k < K_FIXED; k++) {
        float o = off[k * H_FIXED + h];
        float w = fabsf(wid[k * H_FIXED + h]);
        float a = amp[k * H_FIXED + h];
        float d = o - rel;
        sum += a * expf(-w * d * d);
    }
    g_scores[idx] = sum;
}

// Kernel 2: out[h, i, j] = scores[h, S-1 + i - j]
// One float4 store per thread (coalesced); 4 gather reads hit L1/L2
// (scores slice per head is 16.4 KB, reused 2048x).
__global__ void tisa_gather_kernel(float4* __restrict__ out, int S) {
    int j4 = blockIdx.x * blockDim.x + threadIdx.x;   // float4 index within row
    int i  = blockIdx.y;
    int h  = blockIdx.z;
    int S4 = S >> 2;
    if (j4 >= S4) return;

    int j = j4 << 2;
    const float* __restrict__ sc = g_scores + (size_t)h * (2 * S + 1);
    int base = (S - 1) + i - j;   // index for this thread's first (lowest-j) element

    float4 v;
    v.x = __ldg(sc + base);
    v.y = __ldg(sc + base - 1);
    v.z = __ldg(sc + base - 2);
    v.w = __ldg(sc + base - 3);

    size_t out_idx = ((size_t)(h * S + i)) * (size_t)S4 + (size_t)j4;
    out[out_idx] = v;
}

extern "C" void kernel_launch(void* const* d_in, const int* in_sizes, int n_in,
                              void* d_out, int out_size) {
    // Inputs (metadata order): seq_len (unused scalar), offsets [K,H],
    // widths [K,H], amplitudes [K,H]
    const float* off = (const float*)d_in[1];
    const float* wid = (const float*)d_in[2];
    const float* amp = (const float*)d_in[3];
    float* out = (float*)d_out;

    // out_size = H * S * S; H = 16 fixed for this problem
    int S = (int)llround(sqrt((double)out_size / (double)H_FIXED));

    // Kernel 1: tiny scores table
    {
        int total = H_FIXED * (2 * S + 1);
        int threads = 256;
        int blocks = (total + threads - 1) / threads;
        tisa_scores_kernel<<<blocks, threads>>>(off, wid, amp, S);
    }

    // Kernel 2: Toeplitz expansion, float4 stores
    {
        int S4 = S >> 2;                 // float4s per row
        int threads = 256;
        dim3 grid((S4 + threads - 1) / threads, S, H_FIXED);
        tisa_gather_kernel<<<grid, threads>>>((float4*)out, S);
    }
}

// round 3
// speedup vs baseline: 1.1591x; 1.1591x over previous
#include <cuda_runtime.h>
#include <math.h>

#define H_FIXED 16
#define K_FIXED 5
#define MAX_SCORE_ELEMS (H_FIXED * (2 * 4096 + 1))

// Reversed scores table: g_revsc[h][q] = scores[h][2S - q]
// so that out[h,i,j] = scores[h, S-1+i-j] = g_revsc[h, S+1-i+j]  (ascending in j)
__device__ float g_revsc[MAX_SCORE_ELEMS];

// Kernel 1: revsc[h, q] = sum_k amp[k,h] * exp(-|w[k,h]| * (off[k,h] - (S - q))^2)
__global__ void tisa_scores_kernel(const float* __restrict__ off,
                                   const float* __restrict__ wid,
                                   const float* __restrict__ amp,
                                   int S) {
    const int L = 2 * S + 1;
    const int total = H_FIXED * L;
    int idx = blockIdx.x * blockDim.x + threadIdx.x;
    if (idx >= total) return;
    int h = idx / L;
    int q = idx - h * L;
    float rel = (float)(S - q);
    float sum = 0.0f;
#pragma unroll
    for (int k = 0; k < K_FIXED; k++) {
        float o = off[k * H_FIXED + h];
        float w = fabsf(wid[k * H_FIXED + h]);
        float a = amp[k * H_FIXED + h];
        float d = o - rel;
        sum += a * expf(-w * d * d);
    }
    g_revsc[idx] = sum;
}

// Kernel 2: each block copies one output row (h, i):
//   out[h, i, j] = revsc[h, S+1-i+j]   for j = 0..S-1  (unit stride, coalesced)
// Loads are stride-1 LDG (1 wavefront / 128B, L1/L2-resident table);
// stores are stride-1 STG.32 (1 wavefront / 128B).
__global__ void tisa_expand_kernel(float* __restrict__ out, int S) {
    const int i = blockIdx.y;
    const int h = blockIdx.z;
    const int tid = threadIdx.x;
    const int nthr = blockDim.x;

    const float* __restrict__ src = g_revsc + (size_t)h * (2 * S + 1) + (S + 1 - i);
    float* __restrict__ dst = out + ((size_t)h * S + i) * (size_t)S;

#pragma unroll 8
    for (int j = tid; j < S; j += nthr) {
        dst[j] = __ldg(src + j);
    }
}

extern "C" void kernel_launch(void* const* d_in, const int* in_sizes, int n_in,
                              void* d_out, int out_size) {
    // Inputs (metadata order): seq_len (scalar, unused), offsets [K,H],
    // widths [K,H], amplitudes [K,H]
    const float* off = (const float*)d_in[1];
    const float* wid = (const float*)d_in[2];
    const float* amp = (const float*)d_in[3];
    float* out = (float*)d_out;

    // out_size = H * S * S; H = 16 fixed for this problem
    int S = (int)llround(sqrt((double)out_size / (double)H_FIXED));

    // Kernel 1: tiny reversed scores table
    {
        int total = H_FIXED * (2 * S + 1);
        int threads = 256;
        int blocks = (total + threads - 1) / threads;
        tisa_scores_kernel<<<blocks, threads>>>(off, wid, amp, S);
    }

    // Kernel 2: one block per output row, contiguous copy
    {
        dim3 grid(1, S, H_FIXED);
        tisa_expand_kernel<<<grid, 256>>>(out, S);
    }
}

// round 5
// speedup vs baseline: 1.3209x; 1.1396x over previous
#include <cuda_runtime.h>
#include <math.h>

#define H_FIXED 5
#undef H_FIXED
#define H_FIXED 16
#define K_FIXED 5
#define MAX_S 4096
#define L4_OF(S) (2 * (S) + 4)              // per-head padded length (multiple of 4)
#define MAX_L4 (2 * MAX_S + 4)

// 4 phase-shifted copies of the reversed scores table:
//   T[a][h][m] = revsc[h][m + a],  revsc[h][q] = scores[h][2S - q]
// so out[h,i,j] = revsc[h, (S+1-i) + j] = T[a][h][ (off - a) + j ],  a = off & 3,
// and (off - a) is a multiple of 4 -> aligned float4 loads.
__device__ __align__(16) float g_tab[4 * H_FIXED * MAX_L4];

// Kernel 1: compute revsc[h][q] and scatter into the 4 phase copies.
__global__ void tisa_scores_kernel(const float* __restrict__ off,
                                   const float* __restrict__ wid,
                                   const float* __restrict__ amp,
                                   int S) {
    const int L = 2 * S + 1;
    const int total = H_FIXED * L;
    int idx = blockIdx.x * blockDim.x + threadIdx.x;
    if (idx >= total) return;
    int h = idx / L;
    int q = idx - h * L;
    float rel = (float)(S - q);            // revsc[q] = scores[2S - q] -> rel = (2S-q) - S
    float sum = 0.0f;
#pragma unroll
    for (int k = 0; k < K_FIXED; k++) {
        float o = off[k * H_FIXED + h];
        float w = fabsf(wid[k * H_FIXED + h]);
        float a = amp[k * H_FIXED + h];
        float d = o - rel;
        sum += a * expf(-w * d * d);
    }
    const int L4 = L4_OF(S);
#pragma unroll
    for (int a = 0; a < 4; a++) {
        int m = q - a;                      // T[a][h][m] = revsc[h][m + a]
        if (m >= 0)
            g_tab[((size_t)a * H_FIXED + h) * L4 + m] = sum;
    }
}

// Kernel 2: out[h, i, j..j+3] = float4 load from phase table (both sides aligned).
// Each thread handles ELEMS_PER_THREAD float4s for MLP.
#define TPB 256
#define F4_PER_THREAD 2
__global__ void tisa_expand_kernel(float4* __restrict__ out, int S) {
    const int i = blockIdx.y;
    const int h = blockIdx.z;
    const int S4 = S >> 2;

    const int offr = S + 1 - i;            // row offset into revsc
    const int a = offr & 3;
    const int base = offr - a;             // multiple of 4
    const int L4 = L4_OF(S);

    const float4* __restrict__ src = (const float4*)
        (g_tab + ((size_t)a * H_FIXED + h) * L4 + base);
    float4* __restrict__ dst = out + ((size_t)h * S + i) * (size_t)S4;

    int j4 = blockIdx.x * (TPB * F4_PER_THREAD) + threadIdx.x;
#pragma unroll
    for (int u = 0; u < F4_PER_THREAD; u++) {
        dst[j4] = __ldg(src + j4);
        j4 += TPB;
    }
}

extern "C" void kernel_launch(void* const* d_in, const int* in_sizes, int n_in,
                              void* d_out, int out_size) {
    // Inputs (metadata order): seq_len (scalar, unused), offsets [K,H],
    // widths [K,H], amplitudes [K,H]
    const float* off = (const float*)d_in[1];
    const float* wid = (const float*)d_in[2];
    const float* amp = (const float*)d_in[3];

    // out_size = H * S * S; H = 16 fixed for this problem
    int S = (int)llround(sqrt((double)out_size / (double)H_FIXED));

    // Kernel 1: tiny phase-shifted table build
    {
        int total = H_FIXED * (2 * S + 1);
        int threads = 256;
        int blocks = (total + threads - 1) / threads;
        tisa_scores_kernel<<<blocks, threads>>>(off, wid, amp, S);
    }

    // Kernel 2: vectorized Toeplitz expansion
    {
        int S4 = S >> 2;
        int bx = (S4 + TPB * F4_PER_THREAD - 1) / (TPB * F4_PER_THREAD);
        dim3 grid(bx, S, H_FIXED);
        tisa_expand_kernel<<<grid, TPB>>>((float4*)d_out, S);
    }
}